// round 12
// baseline (speedup 1.0000x reference)
#include <cuda_runtime.h>
#include <cuda.h>
#include <cuda_fp16.h>
#include <cstdint>

// Vanilla tanh RNN: h_t = tanh(x_t W_ih^T + b_ih + h_{t-1} W_hh^T + b_hh)
// B=4096, T=256, I=H=64. Output: [hT (B*H) | all h_t (B*T*H)] fp32.
//
// 4-way n-split (R10, 121us) + this round:
//  - own-kt register feedback: warp q's post-tanh C-frag IS A-frag kt=q;
//    LDSM only the other 3 k-tiles (h LDSM 8->6KB/step).
//  - out-STS and x-GEMM(t+1) moved AFTER the per-step barrier (independent
//    work hides the h-publish dependency); convert + h-STS stay before it.
//  - TMA store/load bookkeeping at tl==1 in the post-barrier tail.
//  - x-chunk mbarrier wait deferred to just before convert.

constexpr int Bsz = 4096, T = 256, H = 64;
constexpr int RPB = 16, GRID = Bsz / RPB;     // 256 blocks
constexpr int CH = 4, NCH = T / CH;           // 64 chunks
// smem byte offsets
constexpr int SM_X32 = 0;        // [2][16384] fp32 x staging (TMA, SW128)
constexpr int SM_X16 = 32768;    // [2][4 step][16 rows * 144B] fp16 x tiles
constexpr int SM_H   = 51200;    // [2][16 * 144B] fp16 h tiles
constexpr int SM_O   = 56320;    // [3][16384] fp32 out staging (SW128)
constexpr int SM_MB  = 105472;   // 2 mbarriers
constexpr int SMEM_TOTAL = 105488;

__device__ __forceinline__ uint32_t packh2(float a, float b) {
    __half2 h = __floats2half2_rn(a, b);
    return *reinterpret_cast<uint32_t*>(&h);
}

__device__ __forceinline__ void mma16(float* c, const uint32_t* a, const uint32_t* b) {
    asm volatile(
        "mma.sync.aligned.m16n8k16.row.col.f32.f16.f16.f32 "
        "{%0,%1,%2,%3}, {%4,%5,%6,%7}, {%8,%9}, {%0,%1,%2,%3};"
        : "+f"(c[0]), "+f"(c[1]), "+f"(c[2]), "+f"(c[3])
        : "r"(a[0]), "r"(a[1]), "r"(a[2]), "r"(a[3]), "r"(b[0]), "r"(b[1]));
}

__device__ __forceinline__ void ldsm4(uint32_t* a, uint32_t addr) {
    asm volatile("ldmatrix.sync.aligned.m8n8.x4.shared.b16 {%0,%1,%2,%3}, [%4];"
                 : "=r"(a[0]), "=r"(a[1]), "=r"(a[2]), "=r"(a[3])
                 : "r"(addr));
}

__device__ __forceinline__ float tanh_mufu(float z) {
    float r;
    asm("tanh.approx.f32 %0, %1;" : "=f"(r) : "f"(z));
    return r;
}

__device__ __forceinline__ void tma_load3d(uint32_t sdst, const CUtensorMap* m,
                                           int cx, int cy, int cz, uint32_t mbar) {
    asm volatile(
        "cp.async.bulk.tensor.3d.shared::cta.global.tile.mbarrier::complete_tx::bytes "
        "[%0], [%1, {%2, %3, %4}], [%5];"
        :: "r"(sdst), "l"(m), "r"(cx), "r"(cy), "r"(cz), "r"(mbar) : "memory");
}

__device__ __forceinline__ void tma_store3d(const CUtensorMap* m,
                                            int cx, int cy, int cz, uint32_t ssrc) {
    asm volatile(
        "cp.async.bulk.tensor.3d.global.shared::cta.tile.bulk_group "
        "[%0, {%1, %2, %3}], [%4];"
        :: "l"(m), "r"(cx), "r"(cy), "r"(cz), "r"(ssrc) : "memory");
}

__device__ __forceinline__ void mbar_wait(uint32_t mbar, int parity) {
    asm volatile(
        "{\n\t.reg .pred P;\n\t"
        "W%=:\n\t"
        "mbarrier.try_wait.parity.acquire.cta.shared::cta.b64 P, [%0], %1, 0x989680;\n\t"
        "@!P bra W%=;\n\t}"
        :: "r"(mbar), "r"(parity) : "memory");
}

__global__ void __launch_bounds__(128, 2)
rnn_fused(const __grid_constant__ CUtensorMap xmap,
          const __grid_constant__ CUtensorMap omap,
          const float* __restrict__ h0,
          const float* __restrict__ Wih, const float* __restrict__ Whh,
          const float* __restrict__ bih, const float* __restrict__ bhh,
          float* __restrict__ dout)
{
    extern __shared__ __align__(1024) char smem[];
    const uint32_t sb = (uint32_t)__cvta_generic_to_shared(smem);
    const uint32_t mbA[2] = {sb + SM_MB, sb + SM_MB + 8};

    const int tid  = threadIdx.x;
    const int lane = tid & 31;
    const int q    = tid >> 5;          // warp = col group (16 cols)
    const int gid  = lane >> 2;
    const int tig  = lane & 3;
    const int b0   = blockIdx.x * RPB;
    const int row0 = b0 + gid;

    // ---- TMA prologue: mbars + chunks 0,1 ----
    if (tid == 0) {
        asm volatile("mbarrier.init.shared.b64 [%0], 1;" :: "r"(mbA[0]));
        asm volatile("mbarrier.init.shared.b64 [%0], 1;" :: "r"(mbA[1]));
        asm volatile("fence.proxy.async.shared::cta;" ::: "memory");
        asm volatile("mbarrier.arrive.expect_tx.shared.b64 _, [%0], %1;"
                     :: "r"(mbA[0]), "r"(16384));
        tma_load3d(sb + SM_X32,        &xmap, 0,  b0, 0, mbA[0]);
        tma_load3d(sb + SM_X32 + 8192, &xmap, 32, b0, 0, mbA[0]);
        asm volatile("mbarrier.arrive.expect_tx.shared.b64 _, [%0], %1;"
                     :: "r"(mbA[1]), "r"(16384));
        tma_load3d(sb + SM_X32 + 16384, &xmap, 0,  b0, CH, mbA[1]);
        tma_load3d(sb + SM_X32 + 24576, &xmap, 32, b0, CH, mbA[1]);
    }
    __syncthreads();   // mbar init visible to all before any wait

    // ---- weights for this warp's 16 cols ----
    uint32_t wih[2][4][2], whh[2][4][2];
    float bias[2][2];
    #pragma unroll
    for (int nt = 0; nt < 2; ++nt) {
        const int n = q * 16 + nt * 8 + gid;
        #pragma unroll
        for (int kt = 0; kt < 4; ++kt) {
            const int k = kt * 16 + 2 * tig;
            wih[nt][kt][0] = packh2(Wih[n * H + k],     Wih[n * H + k + 1]);
            wih[nt][kt][1] = packh2(Wih[n * H + k + 8], Wih[n * H + k + 9]);
            whh[nt][kt][0] = packh2(Whh[n * H + k],     Whh[n * H + k + 1]);
            whh[nt][kt][1] = packh2(Whh[n * H + k + 8], Whh[n * H + k + 9]);
        }
        const int col = q * 16 + nt * 8 + 2 * tig;
        bias[nt][0] = bih[col]     + bhh[col];
        bias[nt][1] = bih[col + 1] + bhh[col + 1];
    }

    // ---- h0 -> hbuf[0] (padded fp16 tile, 144B rows) ----
    {
        const int r = tid >> 3, g8 = tid & 7;
        const float* hp = h0 + (size_t)(b0 + r) * H + g8 * 8;
        float4 a = *(const float4*)hp, b2 = *(const float4*)(hp + 4);
        *(uint4*)(smem + SM_H + r * 144 + g8 * 16) =
            make_uint4(packh2(a.x, a.y), packh2(a.z, a.w),
                       packh2(b2.x, b2.y), packh2(b2.z, b2.w));
    }

    // ---- own-kt A-frag of h (kt == q) kept in registers ----
    uint32_t own[4];
    #pragma unroll
    for (int ntl = 0; ntl < 2; ++ntl) {
        const int k = q * 16 + ntl * 8 + 2 * tig;
        float2 v0 = *(const float2*)(h0 + (size_t)row0 * H + k);
        float2 v1 = *(const float2*)(h0 + (size_t)(row0 + 8) * H + k);
        own[ntl * 2 + 0] = packh2(v0.x, v0.y);
        own[ntl * 2 + 1] = packh2(v1.x, v1.y);
    }

    // ---- fp32->fp16 x conversion (thread covers row cr, 8 float cols) ----
    const int cr = tid >> 3, cg = tid & 7;
    const int chalf = cg >> 2;
    auto convert = [&](int buf, int step) {
        const char* src = smem + SM_X32 + buf * 16384 + chalf * 8192 + step * 2048;
        const uint32_t o = (uint32_t)(cr * 128 + (cg & 3) * 32);
        const uint32_t k = (uint32_t)((cr & 7) << 4);
        float4 a  = *(const float4*)(src + ((o)      ^ k));
        float4 b2 = *(const float4*)(src + ((o + 16) ^ k));
        *(uint4*)(smem + SM_X16 + buf * 9216 + step * 2304 + cr * 144 + cg * 16) =
            make_uint4(packh2(a.x, a.y), packh2(a.z, a.w),
                       packh2(b2.x, b2.y), packh2(b2.z, b2.w));
    };

    // ldmatrix lane offset within a 16x64h padded tile
    const int mat = lane >> 3, mr = lane & 7;
    const uint32_t aoff = (uint32_t)(((mat & 1) * 8 + mr) * 144 + (mat >> 1) * 16);
    const uint32_t x16b = sb + SM_X16;
    const uint32_t hbB  = sb + SM_H;

    // ---- prologue: wait chunk0, convert it, initial acc = bias + xW(0) ----
    mbar_wait(mbA[0], 0);
    #pragma unroll
    for (int s = 0; s < CH; ++s) convert(0, s);
    __syncthreads();

    float acc[2][4];
    #pragma unroll
    for (int nt = 0; nt < 2; ++nt) {
        acc[nt][0] = bias[nt][0]; acc[nt][1] = bias[nt][1];
        acc[nt][2] = bias[nt][0]; acc[nt][3] = bias[nt][1];
    }
    #pragma unroll
    for (int kt = 0; kt < 4; ++kt) {
        uint32_t a[4];
        ldsm4(a, x16b + aoff + kt * 32);
        mma16(acc[0], a, wih[0][kt]);
        mma16(acc[1], a, wih[1][kt]);
    }

    int ph[2] = {1, 0};   // next parities for mb0/mb1
    float hval[2][4];

    for (int t = 0; t < T; ++t) {
        const int tl = t & 3, c = t >> 2, cb = c & 1, nb = cb ^ 1, pb = t & 1;

        // ---- h-GEMM: acc += h_{t-1} @ W_hh^T ----
        // A k-tiles: kt==q from registers (own), others via ldmatrix.
        {
            const uint32_t hrd = hbB + pb * 2304 + aoff;
            uint32_t a[4][4];
            #pragma unroll
            for (int kt = 0; kt < 4; ++kt)
                if (kt != q) ldsm4(a[kt], hrd + kt * 32);
            #pragma unroll
            for (int kt = 0; kt < 4; ++kt)
                if (kt == q) {
                    a[kt][0] = own[0]; a[kt][1] = own[1];
                    a[kt][2] = own[2]; a[kt][3] = own[3];
                }
            #pragma unroll
            for (int kt = 0; kt < 4; ++kt) {
                mma16(acc[0], a[kt], whh[0][kt]);
                mma16(acc[1], a[kt], whh[1][kt]);
            }
        }

        // ---- tanh -> own regs + publish h (STS); keep fp32 for out ----
        {
            uint32_t* hw = (uint32_t*)(smem + SM_H + (pb ^ 1) * 2304);
            #pragma unroll
            for (int nt = 0; nt < 2; ++nt) {
                hval[nt][0] = tanh_mufu(acc[nt][0]);
                hval[nt][1] = tanh_mufu(acc[nt][1]);
                hval[nt][2] = tanh_mufu(acc[nt][2]);
                hval[nt][3] = tanh_mufu(acc[nt][3]);
                own[nt * 2 + 0] = packh2(hval[nt][0], hval[nt][1]);
                own[nt * 2 + 1] = packh2(hval[nt][2], hval[nt][3]);
                hw[gid * 36 + q * 8 + nt * 4 + tig]       = own[nt * 2 + 0];
                hw[(gid + 8) * 36 + q * 8 + nt * 4 + tig] = own[nt * 2 + 1];
                acc[nt][0] = bias[nt][0]; acc[nt][1] = bias[nt][1];
                acc[nt][2] = bias[nt][0]; acc[nt][3] = bias[nt][1];
            }
        }

        // ---- convert step tl of next chunk (gates next chunk's TMA issue) ----
        if (c + 1 < NCH) {
            if (tl == 0) { mbar_wait(mbA[nb], ph[nb]); ph[nb] ^= 1; }
            convert(nb, tl);
        }

        __syncthreads();

        // ================= post-barrier tail (independent work) =============
        // TMA bookkeeping at tl==1: store chunk c-1, load chunk c+2.
        if (tl == 1 && tid == 0) {
            if (c > 0) {
                asm volatile("fence.proxy.async.shared::cta;" ::: "memory");
                const int pc = c - 1;
                const uint32_t osrc = sb + SM_O + (pc % 3) * 16384;
                tma_store3d(&omap, 0,  b0, pc * CH, osrc);
                tma_store3d(&omap, 32, b0, pc * CH, osrc + 8192);
                asm volatile("cp.async.bulk.commit_group;" ::: "memory");
            }
            if (c + 2 < NCH) {
                asm volatile("mbarrier.arrive.expect_tx.shared.b64 _, [%0], %1;"
                             :: "r"(mbA[cb]), "r"(16384));
                tma_load3d(sb + SM_X32 + cb * 16384,        &xmap, 0,  b0, (c + 2) * CH, mbA[cb]);
                tma_load3d(sb + SM_X32 + cb * 16384 + 8192, &xmap, 32, b0, (c + 2) * CH, mbA[cb]);
            }
            if (c > 0)
                asm volatile("cp.async.bulk.wait_group.read 1;" ::: "memory");
        }

        // out staging (STS, swizzled) — consumed by TMA store next chunk
        {
            char* otile = smem + SM_O + (c % 3) * 16384 + tl * 2048;
            const uint32_t k2 = (uint32_t)(gid << 4);
            #pragma unroll
            for (int nt = 0; nt < 2; ++nt) {
                const int col = q * 16 + nt * 8 + 2 * tig;
                char* oh = otile + (col >> 5) * 8192;
                const uint32_t co = (uint32_t)((col & 31) * 4);
                *(float2*)(oh + ((gid * 128 + co) ^ k2)) =
                    make_float2(hval[nt][0], hval[nt][1]);
                *(float2*)(oh + (((gid + 8) * 128 + co) ^ k2)) =
                    make_float2(hval[nt][2], hval[nt][3]);
                if (t == T - 1) {
                    *(float2*)(dout + (size_t)row0 * H + col) =
                        make_float2(hval[nt][0], hval[nt][1]);
                    *(float2*)(dout + (size_t)(row0 + 8) * H + col) =
                        make_float2(hval[nt][2], hval[nt][3]);
                }
            }
        }

        // x-GEMM for t+1 (independent of the h chain)
        if (t + 1 < T) {
            const uint32_t xrd = x16b +
                ((tl < 3) ? (uint32_t)(cb * 9216 + (tl + 1) * 2304)
                          : (uint32_t)(nb * 9216)) + aoff;
            #pragma unroll
            for (int kt = 0; kt < 4; ++kt) {
                uint32_t a[4];
                ldsm4(a, xrd + kt * 32);
                mma16(acc[0], a, wih[0][kt]);
                mma16(acc[1], a, wih[1][kt]);
            }
        }
    }

    // ---- final chunk store (after all out-STS of the last chunk) ----
    __syncthreads();
    if (tid == 0) {
        asm volatile("fence.proxy.async.shared::cta;" ::: "memory");
        const int pc = NCH - 1;
        const uint32_t osrc = sb + SM_O + (pc % 3) * 16384;
        tma_store3d(&omap, 0,  b0, pc * CH, osrc);
        tma_store3d(&omap, 32, b0, pc * CH, osrc + 8192);
        asm volatile("cp.async.bulk.commit_group;" ::: "memory");
        asm volatile("cp.async.bulk.wait_group 0;" ::: "memory");
    }
}

typedef CUresult (*tmap_encode_fn)(
    CUtensorMap*, CUtensorMapDataType, cuuint32_t, void*,
    const cuuint64_t*, const cuuint64_t*, const cuuint32_t*, const cuuint32_t*,
    CUtensorMapInterleave, CUtensorMapSwizzle, CUtensorMapL2promotion,
    CUtensorMapFloatOOBfill);

extern "C" void kernel_launch(void* const* d_in, const int* in_sizes, int n_in,
                              void* d_out, int out_size) {
    const float* x   = (const float*)d_in[0];
    const float* h0  = (const float*)d_in[1];
    const float* Wih = (const float*)d_in[2];
    const float* Whh = (const float*)d_in[3];
    const float* bih = (const float*)d_in[4];
    const float* bhh = (const float*)d_in[5];
    float* dout = (float*)d_out;
    (void)in_sizes; (void)n_in; (void)out_size;

    void* fn = nullptr;
    cudaDriverEntryPointQueryResult qr;
    cudaGetDriverEntryPointByVersion("cuTensorMapEncodeTiled", &fn, 12000,
                                     cudaEnableDefault, &qr);
    tmap_encode_fn enc = (tmap_encode_fn)fn;

    // x and out are [B, T, 64] fp32; dims (h, b, t); box (32, 16, 4), SW128.
    cuuint64_t gdim[3] = {64, (cuuint64_t)Bsz, (cuuint64_t)T};
    cuuint64_t gstr[2] = {(cuuint64_t)T * H * sizeof(float),
                          (cuuint64_t)H * sizeof(float)};
    cuuint32_t box[3]  = {32, RPB, CH};
    cuuint32_t estr[3] = {1, 1, 1};

    CUtensorMap xmap, omap;
    enc(&xmap, CU_TENSOR_MAP_DATA_TYPE_FLOAT32, 3, (void*)x,
        gdim, gstr, box, estr, CU_TENSOR_MAP_INTERLEAVE_NONE,
        CU_TENSOR_MAP_SWIZZLE_128B, CU_TENSOR_MAP_L2_PROMOTION_L2_128B,
        CU_TENSOR_MAP_FLOAT_OOB_FILL_NONE);
    enc(&omap, CU_TENSOR_MAP_DATA_TYPE_FLOAT32, 3, (void*)(dout + (size_t)Bsz * H),
        gdim, gstr, box, estr, CU_TENSOR_MAP_INTERLEAVE_NONE,
        CU_TENSOR_MAP_SWIZZLE_128B, CU_TENSOR_MAP_L2_PROMOTION_L2_128B,
        CU_TENSOR_MAP_FLOAT_OOB_FILL_NONE);

    cudaFuncSetAttribute(rnn_fused, cudaFuncAttributeMaxDynamicSharedMemorySize,
                         SMEM_TOTAL);
    rnn_fused<<<GRID, 128, SMEM_TOTAL>>>(xmap, omap, h0, Wih, Whh, bih, bhh, dout);
}

// round 14
// speedup vs baseline: 1.0450x; 1.0450x over previous
#include <cuda_runtime.h>
#include <cuda.h>
#include <cuda_fp16.h>
#include <cstdint>

// Vanilla tanh RNN: h_t = tanh(x_t W_ih^T + b_ih + h_{t-1} W_hh^T + b_hh)
// B=4096, T=256, I=H=64. Output: [hT (B*H) | all h_t (B*T*H)] fp32.
//
// 2-WAY n-split of the R10 skeleton: 256 blocks x 64 threads; each warp owns
// 32 of the 64 hidden cols (4 n-tiles, 32 MMA/step). The 16x64 h/x fp16
// tiles are each read by 2 warps instead of 4 -> per-CTA L1 traffic drops
// 27KB -> 19KB/step.
//
// R12 -> R13 fix: SM_O must be 1024-byte aligned — the SW128 swizzle of the
// TMA store is phase-relative to 1024B atoms, and R12's SM_O=55808 (only
// 512-aligned) de-swizzled the out tile at the wrong phase (output 1 garbage,
// output 0 fine). Restored SM_O=56320.

constexpr int Bsz = 4096, T = 256, H = 64;
constexpr int RPB = 16, GRID = Bsz / RPB;     // 256 blocks
constexpr int CH = 4, NCH = T / CH;           // 64 chunks
constexpr int NT = 64;                        // 2 warps
// smem byte offsets
constexpr int SM_X32 = 0;        // [2][16384] fp32 x staging (TMA, SW128)
constexpr int SM_X16 = 32768;    // [2][4 step][16 rows * 144B] fp16 x tiles
constexpr int SM_H   = 51200;    // [2][16 * 144B] fp16 h tiles
constexpr int SM_O   = 56320;    // [3][16384] fp32 out staging (SW128, 1K-aligned!)
constexpr int SM_MB  = 105472;   // 2 mbarriers
constexpr int SMEM_TOTAL = 105488;

__device__ __forceinline__ uint32_t packh2(float a, float b) {
    __half2 h = __floats2half2_rn(a, b);
    return *reinterpret_cast<uint32_t*>(&h);
}

__device__ __forceinline__ void mma16(float* c, const uint32_t* a, const uint32_t* b) {
    asm volatile(
        "mma.sync.aligned.m16n8k16.row.col.f32.f16.f16.f32 "
        "{%0,%1,%2,%3}, {%4,%5,%6,%7}, {%8,%9}, {%0,%1,%2,%3};"
        : "+f"(c[0]), "+f"(c[1]), "+f"(c[2]), "+f"(c[3])
        : "r"(a[0]), "r"(a[1]), "r"(a[2]), "r"(a[3]), "r"(b[0]), "r"(b[1]));
}

__device__ __forceinline__ void ldsm4(uint32_t* a, uint32_t addr) {
    asm volatile("ldmatrix.sync.aligned.m8n8.x4.shared.b16 {%0,%1,%2,%3}, [%4];"
                 : "=r"(a[0]), "=r"(a[1]), "=r"(a[2]), "=r"(a[3])
                 : "r"(addr));
}

__device__ __forceinline__ float tanh_mufu(float z) {
    float r;
    asm("tanh.approx.f32 %0, %1;" : "=f"(r) : "f"(z));
    return r;
}

__device__ __forceinline__ void tma_load3d(uint32_t sdst, const CUtensorMap* m,
                                           int cx, int cy, int cz, uint32_t mbar) {
    asm volatile(
        "cp.async.bulk.tensor.3d.shared::cta.global.tile.mbarrier::complete_tx::bytes "
        "[%0], [%1, {%2, %3, %4}], [%5];"
        :: "r"(sdst), "l"(m), "r"(cx), "r"(cy), "r"(cz), "r"(mbar) : "memory");
}

__device__ __forceinline__ void tma_store3d(const CUtensorMap* m,
                                            int cx, int cy, int cz, uint32_t ssrc) {
    asm volatile(
        "cp.async.bulk.tensor.3d.global.shared::cta.tile.bulk_group "
        "[%0, {%1, %2, %3}], [%4];"
        :: "l"(m), "r"(cx), "r"(cy), "r"(cz), "r"(ssrc) : "memory");
}

__device__ __forceinline__ void mbar_wait(uint32_t mbar, int parity) {
    asm volatile(
        "{\n\t.reg .pred P;\n\t"
        "W%=:\n\t"
        "mbarrier.try_wait.parity.acquire.cta.shared::cta.b64 P, [%0], %1, 0x989680;\n\t"
        "@!P bra W%=;\n\t}"
        :: "r"(mbar), "r"(parity) : "memory");
}

__global__ void __launch_bounds__(NT, 2)
rnn_fused(const __grid_constant__ CUtensorMap xmap,
          const __grid_constant__ CUtensorMap omap,
          const float* __restrict__ h0,
          const float* __restrict__ Wih, const float* __restrict__ Whh,
          const float* __restrict__ bih, const float* __restrict__ bhh,
          float* __restrict__ dout)
{
    extern __shared__ __align__(1024) char smem[];
    const uint32_t sb = (uint32_t)__cvta_generic_to_shared(smem);
    const uint32_t mbA[2] = {sb + SM_MB, sb + SM_MB + 8};

    const int tid  = threadIdx.x;
    const int lane = tid & 31;
    const int q    = tid >> 5;          // warp = col group (32 cols)
    const int gid  = lane >> 2;
    const int tig  = lane & 3;
    const int b0   = blockIdx.x * RPB;
    const int row0 = b0 + gid;

    // ---- TMA prologue: mbars + chunks 0,1 ----
    if (tid == 0) {
        asm volatile("mbarrier.init.shared.b64 [%0], 1;" :: "r"(mbA[0]));
        asm volatile("mbarrier.init.shared.b64 [%0], 1;" :: "r"(mbA[1]));
        asm volatile("fence.proxy.async.shared::cta;" ::: "memory");
        asm volatile("mbarrier.arrive.expect_tx.shared.b64 _, [%0], %1;"
                     :: "r"(mbA[0]), "r"(16384));
        tma_load3d(sb + SM_X32,        &xmap, 0,  b0, 0, mbA[0]);
        tma_load3d(sb + SM_X32 + 8192, &xmap, 32, b0, 0, mbA[0]);
        asm volatile("mbarrier.arrive.expect_tx.shared.b64 _, [%0], %1;"
                     :: "r"(mbA[1]), "r"(16384));
        tma_load3d(sb + SM_X32 + 16384, &xmap, 0,  b0, CH, mbA[1]);
        tma_load3d(sb + SM_X32 + 24576, &xmap, 32, b0, CH, mbA[1]);
    }
    __syncthreads();   // mbar init visible to all before any wait

    // ---- weights for this warp's 32 cols (4 n-tiles) ----
    uint32_t wih[4][4][2], whh[4][4][2];
    float bias[4][2];
    #pragma unroll
    for (int nt = 0; nt < 4; ++nt) {
        const int n = q * 32 + nt * 8 + gid;
        #pragma unroll
        for (int kt = 0; kt < 4; ++kt) {
            const int k = kt * 16 + 2 * tig;
            wih[nt][kt][0] = packh2(Wih[n * H + k],     Wih[n * H + k + 1]);
            wih[nt][kt][1] = packh2(Wih[n * H + k + 8], Wih[n * H + k + 9]);
            whh[nt][kt][0] = packh2(Whh[n * H + k],     Whh[n * H + k + 1]);
            whh[nt][kt][1] = packh2(Whh[n * H + k + 8], Whh[n * H + k + 9]);
        }
        const int col = q * 32 + nt * 8 + 2 * tig;
        bias[nt][0] = bih[col]     + bhh[col];
        bias[nt][1] = bih[col + 1] + bhh[col + 1];
    }

    // ---- h0 -> hbuf[0] (padded fp16 tile, 144B rows): 16 floats/thread ----
    {
        const int r = tid >> 2;
        #pragma unroll
        for (int j = 0; j < 2; ++j) {
            const int g8 = (tid & 3) * 2 + j;
            const float* hp = h0 + (size_t)(b0 + r) * H + g8 * 8;
            float4 a = *(const float4*)hp, b2 = *(const float4*)(hp + 4);
            *(uint4*)(smem + SM_H + r * 144 + g8 * 16) =
                make_uint4(packh2(a.x, a.y), packh2(a.z, a.w),
                           packh2(b2.x, b2.y), packh2(b2.z, b2.w));
        }
    }

    // ---- fp32->fp16 x conversion: thread covers row cr, 16 float cols ----
    const int cr = tid >> 2;
    auto convert = [&](int buf, int step) {
        #pragma unroll
        for (int j = 0; j < 2; ++j) {
            const int cg = (tid & 3) * 2 + j;
            const int chalf = cg >> 2;
            const char* src = smem + SM_X32 + buf * 16384 + chalf * 8192 + step * 2048;
            const uint32_t o = (uint32_t)(cr * 128 + (cg & 3) * 32);
            const uint32_t k = (uint32_t)((cr & 7) << 4);
            float4 a  = *(const float4*)(src + ((o)      ^ k));
            float4 b2 = *(const float4*)(src + ((o + 16) ^ k));
            *(uint4*)(smem + SM_X16 + buf * 9216 + step * 2304 + cr * 144 + cg * 16) =
                make_uint4(packh2(a.x, a.y), packh2(a.z, a.w),
                           packh2(b2.x, b2.y), packh2(b2.z, b2.w));
        }
    };

    // ldmatrix lane offset within a 16x64h padded tile
    const int mat = lane >> 3, mr = lane & 7;
    const uint32_t aoff = (uint32_t)(((mat & 1) * 8 + mr) * 144 + (mat >> 1) * 16);
    const uint32_t x16b = sb + SM_X16;
    const uint32_t hbB  = sb + SM_H;

    // ---- prologue: wait chunk0, convert it, initial acc = bias + xW(0) ----
    mbar_wait(mbA[0], 0);
    #pragma unroll
    for (int s = 0; s < CH; ++s) convert(0, s);
    __syncthreads();

    float acc[4][4];
    #pragma unroll
    for (int nt = 0; nt < 4; ++nt) {
        acc[nt][0] = bias[nt][0]; acc[nt][1] = bias[nt][1];
        acc[nt][2] = bias[nt][0]; acc[nt][3] = bias[nt][1];
    }
    #pragma unroll
    for (int kt = 0; kt < 4; ++kt) {
        uint32_t a[4];
        ldsm4(a, x16b + aoff + kt * 32);
        #pragma unroll
        for (int nt = 0; nt < 4; ++nt) mma16(acc[nt], a, wih[nt][kt]);
    }

    int ph[2] = {1, 0};   // next parities for mb0/mb1

    for (int t = 0; t < T; ++t) {
        const int tl = t & 3, c = t >> 2, cb = c & 1, nb = cb ^ 1, pb = t & 1;

        // ---- chunk-start TMA bookkeeping (store c-1, load c+2) ----
        if (tl == 0 && tid == 0) {
            if (c > 0) {
                asm volatile("fence.proxy.async.shared::cta;" ::: "memory");
                const int pc = c - 1;
                const uint32_t osrc = sb + SM_O + (pc % 3) * 16384;
                tma_store3d(&omap, 0,  b0, pc * CH, osrc);
                tma_store3d(&omap, 32, b0, pc * CH, osrc + 8192);
                asm volatile("cp.async.bulk.commit_group;" ::: "memory");
            }
            if (c + 2 < NCH) {
                asm volatile("mbarrier.arrive.expect_tx.shared.b64 _, [%0], %1;"
                             :: "r"(mbA[cb]), "r"(16384));
                tma_load3d(sb + SM_X32 + cb * 16384,        &xmap, 0,  b0, (c + 2) * CH, mbA[cb]);
                tma_load3d(sb + SM_X32 + cb * 16384 + 8192, &xmap, 32, b0, (c + 2) * CH, mbA[cb]);
            }
            if (c > 0)
                asm volatile("cp.async.bulk.wait_group.read 1;" ::: "memory");
        }
        if (tl == 0 && c + 1 < NCH) { mbar_wait(mbA[nb], ph[nb]); ph[nb] ^= 1; }

        // ---- h-GEMM: acc += h_{t-1} @ W_hh^T (ldmatrix from hbuf[pb]) ----
        {
            const uint32_t hrd = hbB + pb * 2304 + aoff;
            #pragma unroll
            for (int kt = 0; kt < 4; ++kt) {
                uint32_t a[4];
                ldsm4(a, hrd + kt * 32);
                #pragma unroll
                for (int nt = 0; nt < 4; ++nt) mma16(acc[nt], a, whh[nt][kt]);
            }
        }

        // ---- tanh -> publish h (STS) + out staging (STS, swizzled) ----
        {
            uint32_t* hw = (uint32_t*)(smem + SM_H + (pb ^ 1) * 2304);
            char* otile = smem + SM_O + (c % 3) * 16384 + tl * 2048;
            const uint32_t k2 = (uint32_t)(gid << 4);
            #pragma unroll
            for (int nt = 0; nt < 4; ++nt) {
                const float v0 = tanh_mufu(acc[nt][0]);
                const float v1 = tanh_mufu(acc[nt][1]);
                const float v2 = tanh_mufu(acc[nt][2]);
                const float v3 = tanh_mufu(acc[nt][3]);
                hw[gid * 36 + q * 16 + nt * 4 + tig]       = packh2(v0, v1);
                hw[(gid + 8) * 36 + q * 16 + nt * 4 + tig] = packh2(v2, v3);
                const int col = q * 32 + nt * 8 + 2 * tig;
                char* oh = otile + (col >> 5) * 8192;
                const uint32_t co = (uint32_t)((col & 31) * 4);
                *(float2*)(oh + ((gid * 128 + co) ^ k2))       = make_float2(v0, v1);
                *(float2*)(oh + (((gid + 8) * 128 + co) ^ k2)) = make_float2(v2, v3);
                if (t == T - 1) {
                    *(float2*)(dout + (size_t)row0 * H + col)       = make_float2(v0, v1);
                    *(float2*)(dout + (size_t)(row0 + 8) * H + col) = make_float2(v2, v3);
                }
                acc[nt][0] = bias[nt][0]; acc[nt][1] = bias[nt][1];
                acc[nt][2] = bias[nt][0]; acc[nt][3] = bias[nt][1];
            }
        }

        // ---- x-GEMM for t+1 (independent of the h chain) ----
        if (t + 1 < T) {
            const uint32_t xrd = x16b +
                ((tl < 3) ? (uint32_t)(cb * 9216 + (tl + 1) * 2304)
                          : (uint32_t)(nb * 9216)) + aoff;
            #pragma unroll
            for (int kt = 0; kt < 4; ++kt) {
                uint32_t a[4];
                ldsm4(a, xrd + kt * 32);
                #pragma unroll
                for (int nt = 0; nt < 4; ++nt) mma16(acc[nt], a, wih[nt][kt]);
            }
        }

        // ---- convert step tl of next chunk (off-chain) ----
        if (c + 1 < NCH) convert(nb, tl);

        __syncthreads();
    }

    // ---- final chunk store ----
    if (tid == 0) {
        asm volatile("fence.proxy.async.shared::cta;" ::: "memory");
        const int pc = NCH - 1;
        const uint32_t osrc = sb + SM_O + (pc % 3) * 16384;
        tma_store3d(&omap, 0,  b0, pc * CH, osrc);
        tma_store3d(&omap, 32, b0, pc * CH, osrc + 8192);
        asm volatile("cp.async.bulk.commit_group;" ::: "memory");
        asm volatile("cp.async.bulk.wait_group 0;" ::: "memory");
    }
}

typedef CUresult (*tmap_encode_fn)(
    CUtensorMap*, CUtensorMapDataType, cuuint32_t, void*,
    const cuuint64_t*, const cuuint64_t*, const cuuint32_t*, const cuuint32_t*,
    CUtensorMapInterleave, CUtensorMapSwizzle, CUtensorMapL2promotion,
    CUtensorMapFloatOOBfill);

extern "C" void kernel_launch(void* const* d_in, const int* in_sizes, int n_in,
                              void* d_out, int out_size) {
    const float* x   = (const float*)d_in[0];
    const float* h0  = (const float*)d_in[1];
    const float* Wih = (const float*)d_in[2];
    const float* Whh = (const float*)d_in[3];
    const float* bih = (const float*)d_in[4];
    const float* bhh = (const float*)d_in[5];
    float* dout = (float*)d_out;
    (void)in_sizes; (void)n_in; (void)out_size;

    void* fn = nullptr;
    cudaDriverEntryPointQueryResult qr;
    cudaGetDriverEntryPointByVersion("cuTensorMapEncodeTiled", &fn, 12000,
                                     cudaEnableDefault, &qr);
    tmap_encode_fn enc = (tmap_encode_fn)fn;

    // x and out are [B, T, 64] fp32; dims (h, b, t); box (32, 16, 4), SW128.
    cuuint64_t gdim[3] = {64, (cuuint64_t)Bsz, (cuuint64_t)T};
    cuuint64_t gstr[2] = {(cuuint64_t)T * H * sizeof(float),
                          (cuuint64_t)H * sizeof(float)};
    cuuint32_t box[3]  = {32, RPB, CH};
    cuuint32_t estr[3] = {1, 1, 1};

    CUtensorMap xmap, omap;
    enc(&xmap, CU_TENSOR_MAP_DATA_TYPE_FLOAT32, 3, (void*)x,
        gdim, gstr, box, estr, CU_TENSOR_MAP_INTERLEAVE_NONE,
        CU_TENSOR_MAP_SWIZZLE_128B, CU_TENSOR_MAP_L2_PROMOTION_L2_128B,
        CU_TENSOR_MAP_FLOAT_OOB_FILL_NONE);
    enc(&omap, CU_TENSOR_MAP_DATA_TYPE_FLOAT32, 3, (void*)(dout + (size_t)Bsz * H),
        gdim, gstr, box, estr, CU_TENSOR_MAP_INTERLEAVE_NONE,
        CU_TENSOR_MAP_SWIZZLE_128B, CU_TENSOR_MAP_L2_PROMOTION_L2_128B,
        CU_TENSOR_MAP_FLOAT_OOB_FILL_NONE);

    cudaFuncSetAttribute(rnn_fused, cudaFuncAttributeMaxDynamicSharedMemorySize,
                         SMEM_TOTAL);
    rnn_fused<<<GRID, NT, SMEM_TOTAL>>>(xmap, omap, h0, Wih, Whh, bih, bhh, dout);
}

// round 15
// speedup vs baseline: 1.0639x; 1.0180x over previous
#include <cuda_runtime.h>
#include <cuda.h>
#include <cuda_fp16.h>
#include <cstdint>

// Vanilla tanh RNN: h_t = tanh(x_t W_ih^T + b_ih + h_{t-1} W_hh^T + b_hh)
// B=4096, T=256, I=H=64. Output: [hT (B*H) | all h_t (B*T*H)] fp32.
//
// PING-PONG ROLE ALTERNATION on the R10 skeleton (121.6us best):
// 256 blocks x 256 threads = two 4-warp groups. Group 0 owns even steps,
// group 1 odd steps. Owner runs ONLY the critical chain (ldsm -> 8 MMA ->
// tanh -> publish h). Helper (= owner of step t-1, h values still in regs)
// concurrently does: out-STS for t-1, x-GEMM prep acc=bias+xW(t+1) for its
// next turn, fp32->fp16 converts, TMA bookkeeping. One __syncthreads/step.
// Tiles, swizzles, TMA chunking identical to R10.

constexpr int Bsz = 4096, T = 256, H = 64;
constexpr int RPB = 16, GRID = Bsz / RPB;     // 256 blocks
constexpr int CH = 4, NCH = T / CH;           // 64 chunks
constexpr int NT = 256;                       // 8 warps, 2 role groups
// smem byte offsets (identical to R10; SM_O is 1024-aligned — required by SW128)
constexpr int SM_X32 = 0;        // [2][16384] fp32 x staging (TMA, SW128)
constexpr int SM_X16 = 32768;    // [2][4 step][16 rows * 144B] fp16 x tiles
constexpr int SM_H   = 51200;    // [2][16 * 144B] fp16 h tiles
constexpr int SM_O   = 56320;    // [3][16384] fp32 out staging (SW128)
constexpr int SM_MB  = 105472;   // 2 mbarriers
constexpr int SMEM_TOTAL = 105488;

__device__ __forceinline__ uint32_t packh2(float a, float b) {
    __half2 h = __floats2half2_rn(a, b);
    return *reinterpret_cast<uint32_t*>(&h);
}

__device__ __forceinline__ void mma16(float* c, const uint32_t* a, const uint32_t* b) {
    asm volatile(
        "mma.sync.aligned.m16n8k16.row.col.f32.f16.f16.f32 "
        "{%0,%1,%2,%3}, {%4,%5,%6,%7}, {%8,%9}, {%0,%1,%2,%3};"
        : "+f"(c[0]), "+f"(c[1]), "+f"(c[2]), "+f"(c[3])
        : "r"(a[0]), "r"(a[1]), "r"(a[2]), "r"(a[3]), "r"(b[0]), "r"(b[1]));
}

__device__ __forceinline__ void ldsm4(uint32_t* a, uint32_t addr) {
    asm volatile("ldmatrix.sync.aligned.m8n8.x4.shared.b16 {%0,%1,%2,%3}, [%4];"
                 : "=r"(a[0]), "=r"(a[1]), "=r"(a[2]), "=r"(a[3])
                 : "r"(addr));
}

__device__ __forceinline__ float tanh_mufu(float z) {
    float r;
    asm("tanh.approx.f32 %0, %1;" : "=f"(r) : "f"(z));
    return r;
}

__device__ __forceinline__ void tma_load3d(uint32_t sdst, const CUtensorMap* m,
                                           int cx, int cy, int cz, uint32_t mbar) {
    asm volatile(
        "cp.async.bulk.tensor.3d.shared::cta.global.tile.mbarrier::complete_tx::bytes "
        "[%0], [%1, {%2, %3, %4}], [%5];"
        :: "r"(sdst), "l"(m), "r"(cx), "r"(cy), "r"(cz), "r"(mbar) : "memory");
}

__device__ __forceinline__ void tma_store3d(const CUtensorMap* m,
                                            int cx, int cy, int cz, uint32_t ssrc) {
    asm volatile(
        "cp.async.bulk.tensor.3d.global.shared::cta.tile.bulk_group "
        "[%0, {%1, %2, %3}], [%4];"
        :: "l"(m), "r"(cx), "r"(cy), "r"(cz), "r"(ssrc) : "memory");
}

__device__ __forceinline__ void mbar_wait(uint32_t mbar, int parity) {
    asm volatile(
        "{\n\t.reg .pred P;\n\t"
        "W%=:\n\t"
        "mbarrier.try_wait.parity.acquire.cta.shared::cta.b64 P, [%0], %1, 0x989680;\n\t"
        "@!P bra W%=;\n\t}"
        :: "r"(mbar), "r"(parity) : "memory");
}

__global__ void __launch_bounds__(NT, 2)
rnn_fused(const __grid_constant__ CUtensorMap xmap,
          const __grid_constant__ CUtensorMap omap,
          const float* __restrict__ h0,
          const float* __restrict__ Wih, const float* __restrict__ Whh,
          const float* __restrict__ bih, const float* __restrict__ bhh,
          float* __restrict__ dout)
{
    extern __shared__ __align__(1024) char smem[];
    const uint32_t sb = (uint32_t)__cvta_generic_to_shared(smem);
    const uint32_t mbA[2] = {sb + SM_MB, sb + SM_MB + 8};

    const int tid  = threadIdx.x;
    const int lane = tid & 31;
    const int warp = tid >> 5;
    const int grp  = warp >> 2;         // 0 owns even steps, 1 owns odd
    const int q    = warp & 3;          // col group (16 cols)
    const int glid = tid & 127;         // group-local thread id
    const int gid  = lane >> 2;
    const int tig  = lane & 3;
    const int b0   = blockIdx.x * RPB;
    const int row0 = b0 + gid;

    // ---- TMA prologue: mbars + chunks 0,1 ----
    if (tid == 0) {
        asm volatile("mbarrier.init.shared.b64 [%0], 1;" :: "r"(mbA[0]));
        asm volatile("mbarrier.init.shared.b64 [%0], 1;" :: "r"(mbA[1]));
        asm volatile("fence.proxy.async.shared::cta;" ::: "memory");
        asm volatile("mbarrier.arrive.expect_tx.shared.b64 _, [%0], %1;"
                     :: "r"(mbA[0]), "r"(16384));
        tma_load3d(sb + SM_X32,        &xmap, 0,  b0, 0, mbA[0]);
        tma_load3d(sb + SM_X32 + 8192, &xmap, 32, b0, 0, mbA[0]);
        asm volatile("mbarrier.arrive.expect_tx.shared.b64 _, [%0], %1;"
                     :: "r"(mbA[1]), "r"(16384));
        tma_load3d(sb + SM_X32 + 16384, &xmap, 0,  b0, CH, mbA[1]);
        tma_load3d(sb + SM_X32 + 24576, &xmap, 32, b0, CH, mbA[1]);
    }
    __syncthreads();   // mbar init visible before any wait

    // ---- weights for this warp's 16 cols (2 n-tiles) ----
    uint32_t wih[2][4][2], whh[2][4][2];
    float bias[2][2];
    #pragma unroll
    for (int nt = 0; nt < 2; ++nt) {
        const int n = q * 16 + nt * 8 + gid;
        #pragma unroll
        for (int kt = 0; kt < 4; ++kt) {
            const int k = kt * 16 + 2 * tig;
            wih[nt][kt][0] = packh2(Wih[n * H + k],     Wih[n * H + k + 1]);
            wih[nt][kt][1] = packh2(Wih[n * H + k + 8], Wih[n * H + k + 9]);
            whh[nt][kt][0] = packh2(Whh[n * H + k],     Whh[n * H + k + 1]);
            whh[nt][kt][1] = packh2(Whh[n * H + k + 8], Whh[n * H + k + 9]);
        }
        const int col = q * 16 + nt * 8 + 2 * tig;
        bias[nt][0] = bih[col]     + bhh[col];
        bias[nt][1] = bih[col + 1] + bhh[col + 1];
    }

    // ---- h0 -> hbuf[0] (padded fp16 tile, 144B rows): threads 0-127 ----
    if (tid < 128) {
        const int r = tid >> 3, g8 = tid & 7;
        const float* hp = h0 + (size_t)(b0 + r) * H + g8 * 8;
        float4 a = *(const float4*)hp, b2 = *(const float4*)(hp + 4);
        *(uint4*)(smem + SM_H + r * 144 + g8 * 16) =
            make_uint4(packh2(a.x, a.y), packh2(a.z, a.w),
                       packh2(b2.x, b2.y), packh2(b2.z, b2.w));
    }

    // ---- fp32->fp16 x conversion (group-local: 128 threads per group) ----
    const int cr = glid >> 3, cg = glid & 7;
    const int chalf = cg >> 2;
    auto convert = [&](int buf, int step) {
        const char* src = smem + SM_X32 + buf * 16384 + chalf * 8192 + step * 2048;
        const uint32_t o = (uint32_t)(cr * 128 + (cg & 3) * 32);
        const uint32_t k = (uint32_t)((cr & 7) << 4);
        float4 a  = *(const float4*)(src + ((o)      ^ k));
        float4 b2 = *(const float4*)(src + ((o + 16) ^ k));
        *(uint4*)(smem + SM_X16 + buf * 9216 + step * 2304 + cr * 144 + cg * 16) =
            make_uint4(packh2(a.x, a.y), packh2(a.z, a.w),
                       packh2(b2.x, b2.y), packh2(b2.z, b2.w));
    };

    // ldmatrix lane offset within a 16x64h padded tile
    const int mat = lane >> 3, mr = lane & 7;
    const uint32_t aoff = (uint32_t)(((mat & 1) * 8 + mr) * 144 + (mat >> 1) * 16);
    const uint32_t x16b = sb + SM_X16;
    const uint32_t hbB  = sb + SM_H;

    // ---- prologue: wait chunk0, each group converts 2 sub-steps ----
    mbar_wait(mbA[0], 0);
    convert(0, 2 * grp);
    convert(0, 2 * grp + 1);
    __syncthreads();

    float acc[2][4], hval[2][4];
    // group 0 preps acc = bias + xW(0); group 1 preps at step 0 (helper)
    if (grp == 0) {
        #pragma unroll
        for (int nt = 0; nt < 2; ++nt) {
            acc[nt][0] = bias[nt][0]; acc[nt][1] = bias[nt][1];
            acc[nt][2] = bias[nt][0]; acc[nt][3] = bias[nt][1];
        }
        #pragma unroll
        for (int kt = 0; kt < 4; ++kt) {
            uint32_t a[4];
            ldsm4(a, x16b + aoff + kt * 32);
            mma16(acc[0], a, wih[0][kt]);
            mma16(acc[1], a, wih[1][kt]);
        }
    }

    int ph[2] = {1, 0};   // x-chunk mbar parities (used by group 1 only)

    for (int t = 0; t < T; ++t) {
        const int tl = t & 3, c = t >> 2, cb = c & 1, nb = cb ^ 1, pb = t & 1;

        if (grp == pb) {
            // ================= OWNER: critical chain only =================
            const uint32_t hrd = hbB + pb * 2304 + aoff;
            #pragma unroll
            for (int kt = 0; kt < 4; ++kt) {
                uint32_t a[4];
                ldsm4(a, hrd + kt * 32);
                mma16(acc[0], a, whh[0][kt]);
                mma16(acc[1], a, whh[1][kt]);
            }
            uint32_t* hw = (uint32_t*)(smem + SM_H + (pb ^ 1) * 2304);
            #pragma unroll
            for (int nt = 0; nt < 2; ++nt) {
                hval[nt][0] = tanh_mufu(acc[nt][0]);
                hval[nt][1] = tanh_mufu(acc[nt][1]);
                hval[nt][2] = tanh_mufu(acc[nt][2]);
                hval[nt][3] = tanh_mufu(acc[nt][3]);
                hw[gid * 36 + q * 8 + nt * 4 + tig]       = packh2(hval[nt][0], hval[nt][1]);
                hw[(gid + 8) * 36 + q * 8 + nt * 4 + tig] = packh2(hval[nt][2], hval[nt][3]);
            }
        } else {
            // ================= HELPER: all tail work ======================
            // TMA bookkeeping at tl==1 (helper group is 0 -> tid 0 present)
            if (tl == 1 && tid == 0) {
                if (c > 0) {
                    asm volatile("fence.proxy.async.shared::cta;" ::: "memory");
                    const int pc = c - 1;
                    const uint32_t osrc = sb + SM_O + (pc % 3) * 16384;
                    tma_store3d(&omap, 0,  b0, pc * CH, osrc);
                    tma_store3d(&omap, 32, b0, pc * CH, osrc + 8192);
                    asm volatile("cp.async.bulk.commit_group;" ::: "memory");
                }
                if (c + 2 < NCH) {
                    asm volatile("mbarrier.arrive.expect_tx.shared.b64 _, [%0], %1;"
                                 :: "r"(mbA[cb]), "r"(16384));
                    tma_load3d(sb + SM_X32 + cb * 16384,        &xmap, 0,  b0, (c + 2) * CH, mbA[cb]);
                    tma_load3d(sb + SM_X32 + cb * 16384 + 8192, &xmap, 32, b0, (c + 2) * CH, mbA[cb]);
                }
                if (c > 0)
                    asm volatile("cp.async.bulk.wait_group.read 1;" ::: "memory");
            }
            // x-chunk wait at tl==0 (helper group is 1; the convert readers)
            if (tl == 0 && c + 1 < NCH) { mbar_wait(mbA[nb], ph[nb]); ph[nb] ^= 1; }

            // out-STS for step t-1 (this group owned it; hval in registers)
            if (t > 0) {
                const int td = t - 1, ctd = td >> 2, tld = td & 3;
                char* otile = smem + SM_O + (ctd % 3) * 16384 + tld * 2048;
                const uint32_t k2 = (uint32_t)(gid << 4);
                #pragma unroll
                for (int nt = 0; nt < 2; ++nt) {
                    const int col = q * 16 + nt * 8 + 2 * tig;
                    char* oh = otile + (col >> 5) * 8192;
                    const uint32_t co = (uint32_t)((col & 31) * 4);
                    *(float2*)(oh + ((gid * 128 + co) ^ k2)) =
                        make_float2(hval[nt][0], hval[nt][1]);
                    *(float2*)(oh + (((gid + 8) * 128 + co) ^ k2)) =
                        make_float2(hval[nt][2], hval[nt][3]);
                }
            }

            // convert one sub-step of next chunk
            if (c + 1 < NCH) convert(nb, tl);

            // x-GEMM prep for this group's next owned step (t+1)
            if (t + 1 < T) {
                const int tn = t + 1, cn = tn >> 2, sn = tn & 3;
                const uint32_t xrd = x16b + (uint32_t)((cn & 1) * 9216 + sn * 2304) + aoff;
                #pragma unroll
                for (int nt = 0; nt < 2; ++nt) {
                    acc[nt][0] = bias[nt][0]; acc[nt][1] = bias[nt][1];
                    acc[nt][2] = bias[nt][0]; acc[nt][3] = bias[nt][1];
                }
                #pragma unroll
                for (int kt = 0; kt < 4; ++kt) {
                    uint32_t a[4];
                    ldsm4(a, xrd + kt * 32);
                    mma16(acc[0], a, wih[0][kt]);
                    mma16(acc[1], a, wih[1][kt]);
                }
            }
        }

        __syncthreads();
    }

    // ---- epilogue: group 1 owned t=255 -> out-STS + hT; then final store ----
    if (grp == 1) {
        char* otile = smem + SM_O + ((NCH - 1) % 3) * 16384 + 3 * 2048;
        const uint32_t k2 = (uint32_t)(gid << 4);
        #pragma unroll
        for (int nt = 0; nt < 2; ++nt) {
            const int col = q * 16 + nt * 8 + 2 * tig;
            char* oh = otile + (col >> 5) * 8192;
            const uint32_t co = (uint32_t)((col & 31) * 4);
            *(float2*)(oh + ((gid * 128 + co) ^ k2)) =
                make_float2(hval[nt][0], hval[nt][1]);
            *(float2*)(oh + (((gid + 8) * 128 + co) ^ k2)) =
                make_float2(hval[nt][2], hval[nt][3]);
            *(float2*)(dout + (size_t)row0 * H + col) =
                make_float2(hval[nt][0], hval[nt][1]);
            *(float2*)(dout + (size_t)(row0 + 8) * H + col) =
                make_float2(hval[nt][2], hval[nt][3]);
        }
    }
    __syncthreads();
    if (tid == 0) {
        asm volatile("fence.proxy.async.shared::cta;" ::: "memory");
        const int pc = NCH - 1;
        const uint32_t osrc = sb + SM_O + (pc % 3) * 16384;
        tma_store3d(&omap, 0,  b0, pc * CH, osrc);
        tma_store3d(&omap, 32, b0, pc * CH, osrc + 8192);
        asm volatile("cp.async.bulk.commit_group;" ::: "memory");
        asm volatile("cp.async.bulk.wait_group 0;" ::: "memory");
    }
}

typedef CUresult (*tmap_encode_fn)(
    CUtensorMap*, CUtensorMapDataType, cuuint32_t, void*,
    const cuuint64_t*, const cuuint64_t*, const cuuint32_t*, const cuuint32_t*,
    CUtensorMapInterleave, CUtensorMapSwizzle, CUtensorMapL2promotion,
    CUtensorMapFloatOOBfill);

extern "C" void kernel_launch(void* const* d_in, const int* in_sizes, int n_in,
                              void* d_out, int out_size) {
    const float* x   = (const float*)d_in[0];
    const float* h0  = (const float*)d_in[1];
    const float* Wih = (const float*)d_in[2];
    const float* Whh = (const float*)d_in[3];
    const float* bih = (const float*)d_in[4];
    const float* bhh = (const float*)d_in[5];
    float* dout = (float*)d_out;
    (void)in_sizes; (void)n_in; (void)out_size;

    void* fn = nullptr;
    cudaDriverEntryPointQueryResult qr;
    cudaGetDriverEntryPointByVersion("cuTensorMapEncodeTiled", &fn, 12000,
                                     cudaEnableDefault, &qr);
    tmap_encode_fn enc = (tmap_encode_fn)fn;

    // x and out are [B, T, 64] fp32; dims (h, b, t); box (32, 16, 4), SW128.
    cuuint64_t gdim[3] = {64, (cuuint64_t)Bsz, (cuuint64_t)T};
    cuuint64_t gstr[2] = {(cuuint64_t)T * H * sizeof(float),
                          (cuuint64_t)H * sizeof(float)};
    cuuint32_t box[3]  = {32, RPB, CH};
    cuuint32_t estr[3] = {1, 1, 1};

    CUtensorMap xmap, omap;
    enc(&xmap, CU_TENSOR_MAP_DATA_TYPE_FLOAT32, 3, (void*)x,
        gdim, gstr, box, estr, CU_TENSOR_MAP_INTERLEAVE_NONE,
        CU_TENSOR_MAP_SWIZZLE_128B, CU_TENSOR_MAP_L2_PROMOTION_L2_128B,
        CU_TENSOR_MAP_FLOAT_OOB_FILL_NONE);
    enc(&omap, CU_TENSOR_MAP_DATA_TYPE_FLOAT32, 3, (void*)(dout + (size_t)Bsz * H),
        gdim, gstr, box, estr, CU_TENSOR_MAP_INTERLEAVE_NONE,
        CU_TENSOR_MAP_SWIZZLE_128B, CU_TENSOR_MAP_L2_PROMOTION_L2_128B,
        CU_TENSOR_MAP_FLOAT_OOB_FILL_NONE);

    cudaFuncSetAttribute(rnn_fused, cudaFuncAttributeMaxDynamicSharedMemorySize,
                         SMEM_TOTAL);
    rnn_fused<<<GRID, NT, SMEM_TOTAL>>>(xmap, omap, h0, Wih, Whh, bih, bhh, dout);
}

// round 16
// speedup vs baseline: 1.0956x; 1.0299x over previous
#include <cuda_runtime.h>
#include <cuda.h>
#include <cuda_fp16.h>
#include <cstdint>

// Vanilla tanh RNN: h_t = tanh(x_t W_ih^T + b_ih + h_{t-1} W_hh^T + b_hh)
// B=4096, T=256, I=H=64. Output: [hT (B*H) | all h_t (B*T*H)] fp32.
//
// R10 skeleton (best: 121.6us), 4-way n-split, 256 blocks x 128 threads,
// 2 CTAs/SM. THIS ROUND: step body reordered so __syncthreads sees a drained
// STS queue (B300: BAR.SYNC drains pending STS at 36+36*n_STS for 8 warps):
//   h-GEMM -> tanh+h-STS -> convert -> out-STS -> x-GEMM(t+1, no STS) -> BAR
// TMA bookkeeping moved off warp 0's critical h-chain (to just before BAR);
// x-chunk mbar_wait moved to just before convert (its only consumer).

constexpr int Bsz = 4096, T = 256, H = 64;
constexpr int RPB = 16, GRID = Bsz / RPB;     // 256 blocks
constexpr int CH = 4, NCH = T / CH;           // 64 chunks
constexpr int NT = 128;                       // 4 warps
// smem byte offsets (SM_O 1024-aligned — required by SW128 TMA store phase)
constexpr int SM_X32 = 0;        // [2][16384] fp32 x staging (TMA, SW128)
constexpr int SM_X16 = 32768;    // [2][4 step][16 rows * 144B] fp16 x tiles
constexpr int SM_H   = 51200;    // [2][16 * 144B] fp16 h tiles
constexpr int SM_O   = 56320;    // [3][16384] fp32 out staging (SW128)
constexpr int SM_MB  = 105472;   // 2 mbarriers
constexpr int SMEM_TOTAL = 105488;

__device__ __forceinline__ uint32_t packh2(float a, float b) {
    __half2 h = __floats2half2_rn(a, b);
    return *reinterpret_cast<uint32_t*>(&h);
}

__device__ __forceinline__ void mma16(float* c, const uint32_t* a, const uint32_t* b) {
    asm volatile(
        "mma.sync.aligned.m16n8k16.row.col.f32.f16.f16.f32 "
        "{%0,%1,%2,%3}, {%4,%5,%6,%7}, {%8,%9}, {%0,%1,%2,%3};"
        : "+f"(c[0]), "+f"(c[1]), "+f"(c[2]), "+f"(c[3])
        : "r"(a[0]), "r"(a[1]), "r"(a[2]), "r"(a[3]), "r"(b[0]), "r"(b[1]));
}

__device__ __forceinline__ void ldsm4(uint32_t* a, uint32_t addr) {
    asm volatile("ldmatrix.sync.aligned.m8n8.x4.shared.b16 {%0,%1,%2,%3}, [%4];"
                 : "=r"(a[0]), "=r"(a[1]), "=r"(a[2]), "=r"(a[3])
                 : "r"(addr));
}

__device__ __forceinline__ float tanh_mufu(float z) {
    float r;
    asm("tanh.approx.f32 %0, %1;" : "=f"(r) : "f"(z));
    return r;
}

__device__ __forceinline__ void tma_load3d(uint32_t sdst, const CUtensorMap* m,
                                           int cx, int cy, int cz, uint32_t mbar) {
    asm volatile(
        "cp.async.bulk.tensor.3d.shared::cta.global.tile.mbarrier::complete_tx::bytes "
        "[%0], [%1, {%2, %3, %4}], [%5];"
        :: "r"(sdst), "l"(m), "r"(cx), "r"(cy), "r"(cz), "r"(mbar) : "memory");
}

__device__ __forceinline__ void tma_store3d(const CUtensorMap* m,
                                            int cx, int cy, int cz, uint32_t ssrc) {
    asm volatile(
        "cp.async.bulk.tensor.3d.global.shared::cta.tile.bulk_group "
        "[%0, {%1, %2, %3}], [%4];"
        :: "l"(m), "r"(cx), "r"(cy), "r"(cz), "r"(ssrc) : "memory");
}

__device__ __forceinline__ void mbar_wait(uint32_t mbar, int parity) {
    asm volatile(
        "{\n\t.reg .pred P;\n\t"
        "W%=:\n\t"
        "mbarrier.try_wait.parity.acquire.cta.shared::cta.b64 P, [%0], %1, 0x989680;\n\t"
        "@!P bra W%=;\n\t}"
        :: "r"(mbar), "r"(parity) : "memory");
}

__global__ void __launch_bounds__(NT, 2)
rnn_fused(const __grid_constant__ CUtensorMap xmap,
          const __grid_constant__ CUtensorMap omap,
          const float* __restrict__ h0,
          const float* __restrict__ Wih, const float* __restrict__ Whh,
          const float* __restrict__ bih, const float* __restrict__ bhh,
          float* __restrict__ dout)
{
    extern __shared__ __align__(1024) char smem[];
    const uint32_t sb = (uint32_t)__cvta_generic_to_shared(smem);
    const uint32_t mbA[2] = {sb + SM_MB, sb + SM_MB + 8};

    const int tid  = threadIdx.x;
    const int lane = tid & 31;
    const int q    = tid >> 5;          // warp = col group (16 cols)
    const int gid  = lane >> 2;
    const int tig  = lane & 3;
    const int b0   = blockIdx.x * RPB;
    const int row0 = b0 + gid;

    // ---- TMA prologue: mbars + chunks 0,1 ----
    if (tid == 0) {
        asm volatile("mbarrier.init.shared.b64 [%0], 1;" :: "r"(mbA[0]));
        asm volatile("mbarrier.init.shared.b64 [%0], 1;" :: "r"(mbA[1]));
        asm volatile("fence.proxy.async.shared::cta;" ::: "memory");
        asm volatile("mbarrier.arrive.expect_tx.shared.b64 _, [%0], %1;"
                     :: "r"(mbA[0]), "r"(16384));
        tma_load3d(sb + SM_X32,        &xmap, 0,  b0, 0, mbA[0]);
        tma_load3d(sb + SM_X32 + 8192, &xmap, 32, b0, 0, mbA[0]);
        asm volatile("mbarrier.arrive.expect_tx.shared.b64 _, [%0], %1;"
                     :: "r"(mbA[1]), "r"(16384));
        tma_load3d(sb + SM_X32 + 16384, &xmap, 0,  b0, CH, mbA[1]);
        tma_load3d(sb + SM_X32 + 24576, &xmap, 32, b0, CH, mbA[1]);
    }
    __syncthreads();   // mbar init visible to all before any wait

    // ---- weights for this warp's 16 cols ----
    uint32_t wih[2][4][2], whh[2][4][2];
    float bias[2][2];
    #pragma unroll
    for (int nt = 0; nt < 2; ++nt) {
        const int n = q * 16 + nt * 8 + gid;
        #pragma unroll
        for (int kt = 0; kt < 4; ++kt) {
            const int k = kt * 16 + 2 * tig;
            wih[nt][kt][0] = packh2(Wih[n * H + k],     Wih[n * H + k + 1]);
            wih[nt][kt][1] = packh2(Wih[n * H + k + 8], Wih[n * H + k + 9]);
            whh[nt][kt][0] = packh2(Whh[n * H + k],     Whh[n * H + k + 1]);
            whh[nt][kt][1] = packh2(Whh[n * H + k + 8], Whh[n * H + k + 9]);
        }
        const int col = q * 16 + nt * 8 + 2 * tig;
        bias[nt][0] = bih[col]     + bhh[col];
        bias[nt][1] = bih[col + 1] + bhh[col + 1];
    }

    // ---- h0 -> hbuf[0] (padded fp16 tile, 144B rows) ----
    {
        const int r = tid >> 3, g8 = tid & 7;
        const float* hp = h0 + (size_t)(b0 + r) * H + g8 * 8;
        float4 a = *(const float4*)hp, b2 = *(const float4*)(hp + 4);
        *(uint4*)(smem + SM_H + r * 144 + g8 * 16) =
            make_uint4(packh2(a.x, a.y), packh2(a.z, a.w),
                       packh2(b2.x, b2.y), packh2(b2.z, b2.w));
    }

    // ---- fp32->fp16 x conversion (thread covers row cr, 8 float cols) ----
    const int cr = tid >> 3, cg = tid & 7;
    const int chalf = cg >> 2;
    auto convert = [&](int buf, int step) {
        const char* src = smem + SM_X32 + buf * 16384 + chalf * 8192 + step * 2048;
        const uint32_t o = (uint32_t)(cr * 128 + (cg & 3) * 32);
        const uint32_t k = (uint32_t)((cr & 7) << 4);
        float4 a  = *(const float4*)(src + ((o)      ^ k));
        float4 b2 = *(const float4*)(src + ((o + 16) ^ k));
        *(uint4*)(smem + SM_X16 + buf * 9216 + step * 2304 + cr * 144 + cg * 16) =
            make_uint4(packh2(a.x, a.y), packh2(a.z, a.w),
                       packh2(b2.x, b2.y), packh2(b2.z, b2.w));
    };

    // ldmatrix lane offset within a 16x64h padded tile
    const int mat = lane >> 3, mr = lane & 7;
    const uint32_t aoff = (uint32_t)(((mat & 1) * 8 + mr) * 144 + (mat >> 1) * 16);
    const uint32_t x16b = sb + SM_X16;
    const uint32_t hbB  = sb + SM_H;

    // ---- prologue: wait chunk0, convert it, initial acc = bias + xW(0) ----
    mbar_wait(mbA[0], 0);
    #pragma unroll
    for (int s = 0; s < CH; ++s) convert(0, s);
    __syncthreads();

    float acc[2][4];
    #pragma unroll
    for (int nt = 0; nt < 2; ++nt) {
        acc[nt][0] = bias[nt][0]; acc[nt][1] = bias[nt][1];
        acc[nt][2] = bias[nt][0]; acc[nt][3] = bias[nt][1];
    }
    #pragma unroll
    for (int kt = 0; kt < 4; ++kt) {
        uint32_t a[4];
        ldsm4(a, x16b + aoff + kt * 32);
        mma16(acc[0], a, wih[0][kt]);
        mma16(acc[1], a, wih[1][kt]);
    }

    int ph[2] = {1, 0};   // next parities for mb0/mb1
    float hval[2][4];

    for (int t = 0; t < T; ++t) {
        const int tl = t & 3, c = t >> 2, cb = c & 1, nb = cb ^ 1, pb = t & 1;

        // ---- h-GEMM: acc += h_{t-1} @ W_hh^T (ldmatrix from hbuf[pb]) ----
        {
            const uint32_t hrd = hbB + pb * 2304 + aoff;
            #pragma unroll
            for (int kt = 0; kt < 4; ++kt) {
                uint32_t a[4];
                ldsm4(a, hrd + kt * 32);
                mma16(acc[0], a, whh[0][kt]);
                mma16(acc[1], a, whh[1][kt]);
            }
        }

        // ---- tanh -> publish h (STS) early; keep fp32 values in regs ----
        {
            uint32_t* hw = (uint32_t*)(smem + SM_H + (pb ^ 1) * 2304);
            #pragma unroll
            for (int nt = 0; nt < 2; ++nt) {
                hval[nt][0] = tanh_mufu(acc[nt][0]);
                hval[nt][1] = tanh_mufu(acc[nt][1]);
                hval[nt][2] = tanh_mufu(acc[nt][2]);
                hval[nt][3] = tanh_mufu(acc[nt][3]);
                hw[gid * 36 + q * 8 + nt * 4 + tig]       = packh2(hval[nt][0], hval[nt][1]);
                hw[(gid + 8) * 36 + q * 8 + nt * 4 + tig] = packh2(hval[nt][2], hval[nt][3]);
                acc[nt][0] = bias[nt][0]; acc[nt][1] = bias[nt][1];
                acc[nt][2] = bias[nt][0]; acc[nt][3] = bias[nt][1];
            }
        }

        // ---- convert step tl of next chunk (STS early, drains before BAR) ----
        if (c + 1 < NCH) {
            if (tl == 0) { mbar_wait(mbA[nb], ph[nb]); ph[nb] ^= 1; }
            convert(nb, tl);
        }

        // ---- out staging (STS, swizzled) ----
        {
            char* otile = smem + SM_O + (c % 3) * 16384 + tl * 2048;
            const uint32_t k2 = (uint32_t)(gid << 4);
            #pragma unroll
            for (int nt = 0; nt < 2; ++nt) {
                const int col = q * 16 + nt * 8 + 2 * tig;
                char* oh = otile + (col >> 5) * 8192;
                const uint32_t co = (uint32_t)((col & 31) * 4);
                *(float2*)(oh + ((gid * 128 + co) ^ k2))       = make_float2(hval[nt][0], hval[nt][1]);
                *(float2*)(oh + (((gid + 8) * 128 + co) ^ k2)) = make_float2(hval[nt][2], hval[nt][3]);
                if (t == T - 1) {
                    *(float2*)(dout + (size_t)row0 * H + col)       = make_float2(hval[nt][0], hval[nt][1]);
                    *(float2*)(dout + (size_t)(row0 + 8) * H + col) = make_float2(hval[nt][2], hval[nt][3]);
                }
            }
        }

        // ---- x-GEMM for t+1: pure LDSM/MMA, no STS — drain window ----
        if (t + 1 < T) {
            const uint32_t xrd = x16b +
                ((tl < 3) ? (uint32_t)(cb * 9216 + (tl + 1) * 2304)
                          : (uint32_t)(nb * 9216)) + aoff;
            #pragma unroll
            for (int kt = 0; kt < 4; ++kt) {
                uint32_t a[4];
                ldsm4(a, xrd + kt * 32);
                mma16(acc[0], a, wih[0][kt]);
                mma16(acc[1], a, wih[1][kt]);
            }
        }

        // ---- TMA bookkeeping (tid 0, off the h-chain, just before BAR) ----
        if (tl == 0 && tid == 0) {
            if (c > 0) {
                asm volatile("fence.proxy.async.shared::cta;" ::: "memory");
                const int pc = c - 1;
                const uint32_t osrc = sb + SM_O + (pc % 3) * 16384;
                tma_store3d(&omap, 0,  b0, pc * CH, osrc);
                tma_store3d(&omap, 32, b0, pc * CH, osrc + 8192);
                asm volatile("cp.async.bulk.commit_group;" ::: "memory");
            }
            if (c + 2 < NCH) {
                asm volatile("mbarrier.arrive.expect_tx.shared.b64 _, [%0], %1;"
                             :: "r"(mbA[cb]), "r"(16384));
                tma_load3d(sb + SM_X32 + cb * 16384,        &xmap, 0,  b0, (c + 2) * CH, mbA[cb]);
                tma_load3d(sb + SM_X32 + cb * 16384 + 8192, &xmap, 32, b0, (c + 2) * CH, mbA[cb]);
            }
            if (c > 0)
                asm volatile("cp.async.bulk.wait_group.read 1;" ::: "memory");
        }

        __syncthreads();
    }

    // ---- final chunk store ----
    if (tid == 0) {
        asm volatile("fence.proxy.async.shared::cta;" ::: "memory");
        const int pc = NCH - 1;
        const uint32_t osrc = sb + SM_O + (pc % 3) * 16384;
        tma_store3d(&omap, 0,  b0, pc * CH, osrc);
        tma_store3d(&omap, 32, b0, pc * CH, osrc + 8192);
        asm volatile("cp.async.bulk.commit_group;" ::: "memory");
        asm volatile("cp.async.bulk.wait_group 0;" ::: "memory");
    }
}

typedef CUresult (*tmap_encode_fn)(
    CUtensorMap*, CUtensorMapDataType, cuuint32_t, void*,
    const cuuint64_t*, const cuuint64_t*, const cuuint32_t*, const cuuint32_t*,
    CUtensorMapInterleave, CUtensorMapSwizzle, CUtensorMapL2promotion,
    CUtensorMapFloatOOBfill);

extern "C" void kernel_launch(void* const* d_in, const int* in_sizes, int n_in,
                              void* d_out, int out_size) {
    const float* x   = (const float*)d_in[0];
    const float* h0  = (const float*)d_in[1];
    const float* Wih = (const float*)d_in[2];
    const float* Whh = (const float*)d_in[3];
    const float* bih = (const float*)d_in[4];
    const float* bhh = (const float*)d_in[5];
    float* dout = (float*)d_out;
    (void)in_sizes; (void)n_in; (void)out_size;

    void* fn = nullptr;
    cudaDriverEntryPointQueryResult qr;
    cudaGetDriverEntryPointByVersion("cuTensorMapEncodeTiled", &fn, 12000,
                                     cudaEnableDefault, &qr);
    tmap_encode_fn enc = (tmap_encode_fn)fn;

    // x and out are [B, T, 64] fp32; dims (h, b, t); box (32, 16, 4), SW128.
    cuuint64_t gdim[3] = {64, (cuuint64_t)Bsz, (cuuint64_t)T};
    cuuint64_t gstr[2] = {(cuuint64_t)T * H * sizeof(float),
                          (cuuint64_t)H * sizeof(float)};
    cuuint32_t box[3]  = {32, RPB, CH};
    cuuint32_t estr[3] = {1, 1, 1};

    CUtensorMap xmap, omap;
    enc(&xmap, CU_TENSOR_MAP_DATA_TYPE_FLOAT32, 3, (void*)x,
        gdim, gstr, box, estr, CU_TENSOR_MAP_INTERLEAVE_NONE,
        CU_TENSOR_MAP_SWIZZLE_128B, CU_TENSOR_MAP_L2_PROMOTION_L2_128B,
        CU_TENSOR_MAP_FLOAT_OOB_FILL_NONE);
    enc(&omap, CU_TENSOR_MAP_DATA_TYPE_FLOAT32, 3, (void*)(dout + (size_t)Bsz * H),
        gdim, gstr, box, estr, CU_TENSOR_MAP_INTERLEAVE_NONE,
        CU_TENSOR_MAP_SWIZZLE_128B, CU_TENSOR_MAP_L2_PROMOTION_L2_128B,
        CU_TENSOR_MAP_FLOAT_OOB_FILL_NONE);

    cudaFuncSetAttribute(rnn_fused, cudaFuncAttributeMaxDynamicSharedMemorySize,
                         SMEM_TOTAL);
    rnn_fused<<<GRID, NT, SMEM_TOTAL>>>(xmap, omap, h0, Wih, Whh, bih, bhh, dout);
}